// round 11
// baseline (speedup 1.0000x reference)
#include <cuda_runtime.h>
#include <math_constants.h>

#define LPATCH  (14*14)
#define BATCH   128
#define LTOT    (BATCH*LPATCH)   // 25088
#define NFEAT   784
#define NHID    64

__device__ float g_feat[BATCH * NFEAT];
__device__ float g_hid[BATCH * NHID];

__device__ __forceinline__ void cp_async16(void* sptr, const void* gptr) {
    unsigned s = (unsigned)__cvta_generic_to_shared(sptr);
    asm volatile("cp.async.cg.shared.global [%0], [%1], 16;\n" :: "r"(s), "l"(gptr));
}

// result = co*own + cp*partner (complex MAC)
#define CMAC(nx, ny, cox, coy, cpx, cpy, ox, oy, qx, qy)             \
    nx = (cox)*(ox) - (coy)*(oy) + (cpx)*(qx) - (cpy)*(qy);          \
    ny = (cox)*(oy) + (coy)*(ox) + (cpx)*(qy) + (cpy)*(qx);

#define LOCAL_GATE(u, lox, loy, hix, hiy) do {                        \
    float _lx = (u).x*(lox) + (u).y*(loy) - (u).z*(hix) - (u).w*(hiy);\
    float _ly = (u).x*(loy) - (u).y*(lox) - (u).z*(hiy) + (u).w*(hix);\
    float _hx = (u).z*(lox) - (u).w*(loy) + (u).x*(hix) - (u).y*(hiy);\
    float _hy = (u).z*(loy) + (u).w*(lox) + (u).x*(hiy) + (u).y*(hix);\
    (lox)=_lx; (loy)=_ly; (hix)=_hx; (hiy)=_hy;                       \
} while (0)

// inverse of the CNOT-ring basis permutation, packed as nibbles
#define SIGMA_INV_PACKED 0x497A2F1C85B6E3D0ull

// ============================================================================
// Circuit: 4 threads per patch, 4 amplitudes per thread. 392 blocks x 256.
// Layer 0 + ring 0 folded into init; layer 4 folded into measurement;
// ring CNOTs folded into neighbor gates where possible (R9 algebra).
// ============================================================================
__global__ void __launch_bounds__(256) circuit_kernel(
    const float* __restrict__ x,      // [128,1,28,28]
    const float* __restrict__ w,      // [60]
    float4* __restrict__ feat)        // [LTOT] float4
{
    __shared__ float4 um[16];
    __shared__ float  meas[4][3];

    const int t = threadIdx.x;
    if (t < 16) {
        int l = t >> 2, q = t & 3;
        float a = w[l * 12 + q], bb = w[l * 12 + 4 + q], c = w[l * 12 + 8 + q];
        float sP, cP, sQ, cQ, sB, cB;
        sincosf(0.5f * (a + c), &sP, &cP);
        sincosf(0.5f * (a - c), &sQ, &cQ);
        sincosf(0.5f * bb,      &sB, &cB);
        um[t] = make_float4(cB * cP, sB * cQ, cB * sP, sB * sQ);
    } else if (t < 20) {
        int q = t - 16;
        float a = w[48 + q], bb = w[48 + 4 + q], c = w[48 + 8 + q];
        float sa, ca, sb, cb, sc, cc;
        sincosf(a, &sa, &ca);
        sincosf(bb, &sb, &cb);
        sincosf(c, &sc, &cc);
        meas[q][0] =  cc * ca - sc * cb * sa;
        meas[q][1] = -cc * sa - sc * cb * ca;
        meas[q][2] =  sc * sb;
    }
    __syncthreads();

    const unsigned FULL = 0xffffffffu;
    const int g     = blockIdx.x * 256 + t;
    const int patch = g >> 2;
    const int s     = g & 3;
    const int lane  = t & 31;

    const int b  = patch / LPATCH;
    const int p  = patch - b * LPATCH;
    const int pi = p / 14, pj = p - pi * 14;

    const float* xb = x + b * 784 + (2 * pi) * 28 + 2 * pj;
    float xpix = xb[(s >> 1) * 28 + (s & 1)];
    float hs_l, hc_l;
    __sincosf(CUDART_PI_F * xpix, &hs_l, &hc_l);

    int base = lane & ~3;
    float hcq[4], hsq[4];
#pragma unroll
    for (int q = 0; q < 4; q++) {
        hcq[q] = __shfl_sync(FULL, hc_l, base + q);
        hsq[q] = __shfl_sync(FULL, hs_l, base + q);
    }

    // init: layer 0 folded into per-qubit vectors, ring 0 as permutation
    float v0lx, v0ly, v0hx, v0hy, v1lx, v1ly, v1hx, v1hy;
    float v2lx, v2ly, v2hx, v2hy, v3lx, v3ly, v3hx, v3hy;
    {
        float4 u;
        u = um[0];
        v0lx = hcq[0]*u.x + hsq[0]*u.w;  v0ly = -hcq[0]*u.y + hsq[0]*u.z;
        v0hx = hcq[0]*u.z + hsq[0]*u.y;  v0hy =  hcq[0]*u.w - hsq[0]*u.x;
        u = um[1];
        v1lx = hcq[1]*u.x + hsq[1]*u.w;  v1ly = -hcq[1]*u.y + hsq[1]*u.z;
        v1hx = hcq[1]*u.z + hsq[1]*u.y;  v1hy =  hcq[1]*u.w - hsq[1]*u.x;
        u = um[2];
        v2lx = hcq[2]*u.x + hsq[2]*u.w;  v2ly = -hcq[2]*u.y + hsq[2]*u.z;
        v2hx = hcq[2]*u.z + hsq[2]*u.y;  v2hy =  hcq[2]*u.w - hsq[2]*u.x;
        u = um[3];
        v3lx = hcq[3]*u.x + hsq[3]*u.w;  v3ly = -hcq[3]*u.y + hsq[3]*u.z;
        v3hx = hcq[3]*u.z + hsq[3]*u.y;  v3hy =  hcq[3]*u.w - hsq[3]*u.x;
    }

    float ax[4], ay[4];
#pragma unroll
    for (int r = 0; r < 4; r++) {
        int j = (s << 2) | r;
        int i = (int)((SIGMA_INV_PACKED >> (4 * j)) & 15ull);
        float w0x = (i & 8) ? v0hx : v0lx,  w0y = (i & 8) ? v0hy : v0ly;
        float w1x = (i & 4) ? v1hx : v1lx,  w1y = (i & 4) ? v1hy : v1ly;
        float w2x = (i & 2) ? v2hx : v2lx,  w2y = (i & 2) ? v2hy : v2ly;
        float w3x = (i & 1) ? v3hx : v3lx,  w3y = (i & 1) ? v3hy : v3ly;
        float tx = w0x * w1x - w0y * w1y;
        float ty = w0x * w1y + w0y * w1x;
        float ux_ = tx * w2x - ty * w2y;
        float uy_ = tx * w2y + ty * w2x;
        ax[r] = ux_ * w3x - uy_ * w3y;
        ay[r] = ux_ * w3y + uy_ * w3x;
    }

#pragma unroll
    for (int l = 1; l <= 3; l++) {
        {   // gate q0; layers 2,3 fold previous ring's CNOT(q3->q0)
            float4 u = um[l * 4 + 0];
            float coy = (s & 2) ? u.y : -u.y;
            float cpx = (s & 2) ? u.z : -u.z;
            const bool fold30 = (l >= 2);
#pragma unroll
            for (int r = 0; r < 4; r++) {
                float qx = __shfl_xor_sync(FULL, ax[r], 2);
                float qy = __shfl_xor_sync(FULL, ay[r], 2);
                float nx_, ny_;
                if (fold30 && (r & 1)) {
                    CMAC(nx_, ny_, cpx, u.w, u.x, coy, ax[r], ay[r], qx, qy);
                } else {
                    CMAC(nx_, ny_, u.x, coy, cpx, u.w, ax[r], ay[r], qx, qy);
                }
                ax[r] = nx_; ay[r] = ny_;
            }
        }
        {   // gate q1 with same-layer CNOT(q0->q1) folded
            float4 u = um[l * 4 + 1];
            bool ctrl = (s & 2) != 0;
            bool row  = (((s & 1) != 0) != ctrl);
            float dy = row ? u.y : -u.y;
            float oz = row ? u.z : -u.z;
            float cox = ctrl ? oz  : u.x;
            float coy = ctrl ? u.w : dy;
            float cpx = ctrl ? u.x : oz;
            float cpy = ctrl ? dy  : u.w;
#pragma unroll
            for (int r = 0; r < 4; r++) {
                float qx = __shfl_xor_sync(FULL, ax[r], 1);
                float qy = __shfl_xor_sync(FULL, ay[r], 1);
                float nx_, ny_;
                CMAC(nx_, ny_, cox, coy, cpx, cpy, ax[r], ay[r], qx, qy);
                ax[r] = nx_; ay[r] = ny_;
            }
        }
        {   // local gates q2, q3
            float4 u2 = um[l * 4 + 2];
            LOCAL_GATE(u2, ax[0], ay[0], ax[2], ay[2]);
            LOCAL_GATE(u2, ax[1], ay[1], ax[3], ay[3]);
            float4 u3 = um[l * 4 + 3];
            LOCAL_GATE(u3, ax[0], ay[0], ax[1], ay[1]);
            LOCAL_GATE(u3, ax[2], ay[2], ax[3], ay[3]);
        }
        if (s & 1) {    // CNOT(q1->q2)
            float tx;
            tx = ax[0]; ax[0] = ax[2]; ax[2] = tx;
            tx = ay[0]; ay[0] = ay[2]; ay[2] = tx;
            tx = ax[1]; ax[1] = ax[3]; ax[3] = tx;
            tx = ay[1]; ay[1] = ay[3]; ay[3] = tx;
        }
        {   // CNOT(q2->q3)
            float tx;
            tx = ax[2]; ax[2] = ax[3]; ax[3] = tx;
            tx = ay[2]; ay[2] = ay[3]; ay[3] = tx;
        }
        if (l == 3) {   // last ring's CNOT(q3->q0): explicit
            ax[1] = __shfl_xor_sync(FULL, ax[1], 2);
            ay[1] = __shfl_xor_sync(FULL, ay[1], 2);
            ax[3] = __shfl_xor_sync(FULL, ax[3], 2);
            ay[3] = __shfl_xor_sync(FULL, ay[3], 2);
        }
    }

    // layer-4-folded measurement
    float pr[4];
#pragma unroll
    for (int r = 0; r < 4; r++) pr[r] = ax[r] * ax[r] + ay[r] * ay[r];

    float e0, e1, e2, e3;
    {
        float zc = 0.f, xc = 0.f, yc = 0.f;
#pragma unroll
        for (int r = 0; r < 4; r++) {
            float qx = __shfl_xor_sync(FULL, ax[r], 2);
            float qy = __shfl_xor_sync(FULL, ay[r], 2);
            zc += pr[r];
            xc += ax[r] * qx + ay[r] * qy;
            yc += ax[r] * qy - ay[r] * qx;
        }
        if (s & 2) { zc = -zc; yc = -yc; }
        e0 = meas[0][0] * zc + meas[0][1] * xc + meas[0][2] * yc;
    }
    {
        float zc = 0.f, xc = 0.f, yc = 0.f;
#pragma unroll
        for (int r = 0; r < 4; r++) {
            float qx = __shfl_xor_sync(FULL, ax[r], 1);
            float qy = __shfl_xor_sync(FULL, ay[r], 1);
            zc += pr[r];
            xc += ax[r] * qx + ay[r] * qy;
            yc += ax[r] * qy - ay[r] * qx;
        }
        if (s & 1) { zc = -zc; yc = -yc; }
        e1 = meas[1][0] * zc + meas[1][1] * xc + meas[1][2] * yc;
    }
    {
        float zc = pr[0] + pr[1] - pr[2] - pr[3];
        float xc = 2.f * (ax[0]*ax[2] + ay[0]*ay[2] + ax[1]*ax[3] + ay[1]*ay[3]);
        float yc = 2.f * (ax[0]*ay[2] - ay[0]*ax[2] + ax[1]*ay[3] - ay[1]*ax[3]);
        e2 = meas[2][0] * zc + meas[2][1] * xc + meas[2][2] * yc;
    }
    {
        float zc = pr[0] - pr[1] + pr[2] - pr[3];
        float xc = 2.f * (ax[0]*ax[1] + ay[0]*ay[1] + ax[2]*ax[3] + ay[2]*ay[3]);
        float yc = 2.f * (ax[0]*ay[1] - ay[0]*ax[1] + ax[2]*ay[3] - ay[2]*ax[3]);
        e3 = meas[3][0] * zc + meas[3][1] * xc + meas[3][2] * yc;
    }
    e0 += __shfl_xor_sync(FULL, e0, 1);
    e1 += __shfl_xor_sync(FULL, e1, 1);
    e2 += __shfl_xor_sync(FULL, e2, 1);
    e3 += __shfl_xor_sync(FULL, e3, 1);
    e0 += __shfl_xor_sync(FULL, e0, 2);
    e1 += __shfl_xor_sync(FULL, e1, 2);
    e2 += __shfl_xor_sync(FULL, e2, 2);
    e3 += __shfl_xor_sync(FULL, e3, 2);

    if (s == 0)
        feat[patch] = make_float4(e0, e1, e2, e3);
}

// ============================================================================
// fc1: 1024 blocks x 256 thr. Block = (row b, 8-neuron group g).
// w1 slice (25 KB) + feat row (3 KB) prefetched via cp.async into smem.
// 8 warps, one neuron each. ~28 KB smem -> 8 blocks/SM resident.
// ============================================================================
#define FC1_SMEM (8 * NFEAT * 4 + NFEAT * 4)   // 25088 + 3136 = 28224 B

__global__ void __launch_bounds__(256) fc1_kernel(
    const float* __restrict__ feat,   // [128,784]
    const float* __restrict__ w1,     // [64,784]
    const float* __restrict__ b1,     // [64]
    float* __restrict__ hid)          // [128,64]
{
    extern __shared__ float sm[];
    float* w1s   = sm;                 // 8*784
    float* feats = sm + 8 * NFEAT;     // 784

    const int t = threadIdx.x;
    const int b = blockIdx.x >> 3;
    const int g = blockIdx.x & 7;
    const int n0 = g * 8;

    // prefetch w1 slice (1568 float4) + feat row (196 float4)
    const float* w1g = w1 + n0 * NFEAT;
#pragma unroll
    for (int i = t; i < (8 * NFEAT) / 4; i += 256)
        cp_async16(w1s + i * 4, w1g + i * 4);
    if (t < NFEAT / 4)
        cp_async16(feats + t * 4, feat + b * NFEAT + t * 4);
    asm volatile("cp.async.commit_group;\n" ::: "memory");
    asm volatile("cp.async.wait_group 0;\n" ::: "memory");
    __syncthreads();

    const int warp = t >> 5, lane = t & 31;
    const float4* fv = reinterpret_cast<const float4*>(feats);
    const float4* wv = reinterpret_cast<const float4*>(w1s + warp * NFEAT);

    float acc = 0.f;
    if (lane < 28) {
#pragma unroll
        for (int j = 0; j < 7; j++) {
            int k = j * 28 + lane;
            float4 fa = fv[k];
            float4 ww = wv[k];
            acc = fmaf(fa.x, ww.x, fmaf(fa.y, ww.y, fmaf(fa.z, ww.z, fmaf(fa.w, ww.w, acc))));
        }
    }
#pragma unroll
    for (int off = 16; off > 0; off >>= 1)
        acc += __shfl_xor_sync(0xffffffffu, acc, off);

    if (lane == 0)
        hid[b * NHID + n0 + warp] = fmaxf(acc + b1[n0 + warp], 0.f);
}

// ============================================================================
// fc2: warp per (row, output). 1280 warps = 160 blocks x 256.
// ============================================================================
__global__ void __launch_bounds__(256) fc2_kernel(
    const float* __restrict__ hid,    // [128,64]
    const float* __restrict__ w2,     // [10,64]
    const float* __restrict__ b2,     // [10]
    float* __restrict__ out)          // [128,10]
{
    int gtid = blockIdx.x * blockDim.x + threadIdx.x;
    int warp = gtid >> 5;
    int lane = gtid & 31;
    if (warp >= BATCH * 10) return;
    int b = warp / 10;
    int o = warp - b * 10;

    float acc = 0.f;
    if (lane < 16) {
        float4 h  = reinterpret_cast<const float4*>(hid + b * NHID)[lane];
        float4 ww = reinterpret_cast<const float4*>(w2 + o * NHID)[lane];
        acc = h.x * ww.x + h.y * ww.y + h.z * ww.z + h.w * ww.w;
    }
#pragma unroll
    for (int off = 8; off > 0; off >>= 1)
        acc += __shfl_xor_sync(0xffffffffu, acc, off);

    if (lane == 0)
        out[b * 10 + o] = acc + b2[o];
}

extern "C" void kernel_launch(void* const* d_in, const int* in_sizes, int n_in,
                              void* d_out, int out_size) {
    const float* x     = (const float*)d_in[0];
    const float* w     = (const float*)d_in[1];
    const float* fc1_w = (const float*)d_in[2];
    const float* fc1_b = (const float*)d_in[3];
    const float* fc2_w = (const float*)d_in[4];
    const float* fc2_b = (const float*)d_in[5];
    float* out = (float*)d_out;

    circuit_kernel<<<LTOT * 4 / 256, 256>>>(x, w, (float4*)g_feat);
    fc1_kernel<<<BATCH * 8, 256, FC1_SMEM>>>(g_feat, fc1_w, fc1_b, g_hid);
    fc2_kernel<<<160, 256>>>(g_hid, fc2_w, fc2_b, out);
}

// round 15
// speedup vs baseline: 1.2820x; 1.2820x over previous
#include <cuda_runtime.h>
#include <math_constants.h>

#define LPATCH  (14*14)
#define BATCH   128
#define NFEAT   784
#define NHID    64

// Dynamic smem layout (bytes)
#define FEAT_OFF 0               // 784 floats = 3136 B
#define W1_OFF   3136            // 64*784 floats = 200704 B
#define W2_OFF   203840          // 10*64 floats = 2560 B
#define B1_OFF   206400          // 64 floats
#define HID_OFF  206656          // 64 floats
#define SMEM_TOTAL 206912

__device__ __forceinline__ void cp_async16(void* sptr, const void* gptr) {
    unsigned s = (unsigned)__cvta_generic_to_shared(sptr);
    asm volatile("cp.async.cg.shared.global [%0], [%1], 16;\n" :: "r"(s), "l"(gptr));
}

// Full complex 2x2 on an in-register amplitude pair (proven R7 code)
#define LOCAL_GATE(u, lox, loy, hix, hiy) do {                        \
    float _lx = (u).x*(lox) + (u).y*(loy) - (u).z*(hix) - (u).w*(hiy);\
    float _ly = (u).x*(loy) - (u).y*(lox) - (u).z*(hiy) + (u).w*(hix);\
    float _hx = (u).z*(lox) - (u).w*(loy) + (u).x*(hix) - (u).y*(hiy);\
    float _hy = (u).z*(loy) + (u).w*(lox) + (u).x*(hiy) + (u).y*(hix);\
    (lox)=_lx; (loy)=_ly; (hix)=_hx; (hiy)=_hy;                       \
} while (0)

// One block per batch row: 832 threads.
// Phase 0: cp.async prefetch w1/w2/b1 (drains during phases 1-3)
// Phase 1: um[20] gate constants
// Phase 2: warps 0-1 simulate the 16 columns of the fixed circuit unitary V
// Phase 3: all threads build A_q = Re(W^dag V^dag Z_q V W)  (4 x 16x16 real)
// Phase 4: circuit = quadratic forms: thread (patch,q) does e_q = m^T A_q m
// Phase 5: fc1 from smem; Phase 6: fc2
__global__ void __launch_bounds__(832, 1) fused_kernel(
    const float* __restrict__ x,      // [128,1,28,28]
    const float* __restrict__ w,      // [60]
    const float* __restrict__ w1,     // [64,784]
    const float* __restrict__ b1,     // [64]
    const float* __restrict__ w2,     // [10,64]
    const float* __restrict__ b2,     // [10]
    float* __restrict__ out)          // [128,10]
{
    extern __shared__ char smem_raw[];
    float* feats = reinterpret_cast<float*>(smem_raw + FEAT_OFF);
    float* w1s   = reinterpret_cast<float*>(smem_raw + W1_OFF);
    float* w2s   = reinterpret_cast<float*>(smem_raw + W2_OFF);
    float* b1s   = reinterpret_cast<float*>(smem_raw + B1_OFF);
    float* hids  = reinterpret_cast<float*>(smem_raw + HID_OFF);

    __shared__ float4 um[20];                         // fused yzy, 5 layers x 4 qubits
    __shared__ __align__(16) float2 Vs[16][16];       // V[i][j]
    __shared__ __align__(16) float  Aq[4][16][16];    // real quadratic forms

    const int t = threadIdx.x;
    const int b = blockIdx.x;
    const unsigned FULL = 0xffffffffu;

    // ---- 0. fire-and-forget weight prefetch ----
    for (int i = t; i < (NHID * NFEAT) / 4; i += 832)
        cp_async16(w1s + i * 4, w1 + i * 4);
    if (t < 160) cp_async16(w2s + t * 4, w2 + t * 4);
    if (t < 16)  cp_async16(b1s + t * 4, b1 + t * 4);
    asm volatile("cp.async.commit_group;\n" ::: "memory");

    // ---- 1. gate constants: fused U = Ry(c)Rz(b)Ry(a) per (layer, qubit) ----
    if (t < 20) {
        int l = t >> 2, q = t & 3;
        float a = w[l * 12 + q], bb = w[l * 12 + 4 + q], c = w[l * 12 + 8 + q];
        float sP, cP, sQ, cQ, sB, cB;
        sincosf(0.5f * (a + c), &sP, &cP);
        sincosf(0.5f * (a - c), &sQ, &cQ);
        sincosf(0.5f * bb,      &sB, &cB);
        um[t] = make_float4(cB * cP, sB * cQ, cB * sP, sB * sQ);
    }
    __syncthreads();

    // ---- 2. simulate V columns: thread (col j = t>>2, s = t&3), amps i=(s<<2)|r ----
    if (t < 64) {
        const int j = t >> 2;
        const int s = t & 3;
        float ax[4], ay[4];
#pragma unroll
        for (int r = 0; r < 4; r++) {
            ax[r] = (((s << 2) | r) == j) ? 1.f : 0.f;
            ay[r] = 0.f;
        }
#pragma unroll
        for (int l = 0; l < 5; l++) {
            {   // gate q0 (thread bit 2, shfl mask 2)
                float4 u = um[l * 4 + 0];
                bool bt = (s & 2) != 0;
                float sy = bt ? u.y : -u.y;
                float sz = bt ? u.z : -u.z;
#pragma unroll
                for (int r = 0; r < 4; r++) {
                    float px = __shfl_xor_sync(FULL, ax[r], 2);
                    float py = __shfl_xor_sync(FULL, ay[r], 2);
                    float nx_ = u.x * ax[r] - sy * ay[r] + sz * px - u.w * py;
                    float ny_ = u.x * ay[r] + sy * ax[r] + sz * py + u.w * px;
                    ax[r] = nx_; ay[r] = ny_;
                }
            }
            {   // gate q1 (thread bit 1, shfl mask 1)
                float4 u = um[l * 4 + 1];
                bool bt = (s & 1) != 0;
                float sy = bt ? u.y : -u.y;
                float sz = bt ? u.z : -u.z;
#pragma unroll
                for (int r = 0; r < 4; r++) {
                    float px = __shfl_xor_sync(FULL, ax[r], 1);
                    float py = __shfl_xor_sync(FULL, ay[r], 1);
                    float nx_ = u.x * ax[r] - sy * ay[r] + sz * px - u.w * py;
                    float ny_ = u.x * ay[r] + sy * ax[r] + sz * py + u.w * px;
                    ax[r] = nx_; ay[r] = ny_;
                }
            }
            {   // local gates q2, q3
                float4 u2 = um[l * 4 + 2];
                LOCAL_GATE(u2, ax[0], ay[0], ax[2], ay[2]);
                LOCAL_GATE(u2, ax[1], ay[1], ax[3], ay[3]);
                float4 u3 = um[l * 4 + 3];
                LOCAL_GATE(u3, ax[0], ay[0], ax[1], ay[1]);
                LOCAL_GATE(u3, ax[2], ay[2], ax[3], ay[3]);
            }
            if (l < 4) {    // CNOT ring
#pragma unroll
                for (int r = 0; r < 4; r++) {      // C(q0->q1)
                    float px = __shfl_xor_sync(FULL, ax[r], 1);
                    float py = __shfl_xor_sync(FULL, ay[r], 1);
                    if (s & 2) { ax[r] = px; ay[r] = py; }
                }
                if (s & 1) {                        // C(q1->q2)
                    float tx;
                    tx = ax[0]; ax[0] = ax[2]; ax[2] = tx;
                    tx = ay[0]; ay[0] = ay[2]; ay[2] = tx;
                    tx = ax[1]; ax[1] = ax[3]; ax[3] = tx;
                    tx = ay[1]; ay[1] = ay[3]; ay[3] = tx;
                }
                {                                   // C(q2->q3)
                    float tx;
                    tx = ax[2]; ax[2] = ax[3]; ax[3] = tx;
                    tx = ay[2]; ay[2] = ay[3]; ay[3] = tx;
                }
                // C(q3->q0)
                ax[1] = __shfl_xor_sync(FULL, ax[1], 2);
                ay[1] = __shfl_xor_sync(FULL, ay[1], 2);
                ax[3] = __shfl_xor_sync(FULL, ax[3], 2);
                ay[3] = __shfl_xor_sync(FULL, ay[3], 2);
            }
        }
#pragma unroll
        for (int r = 0; r < 4; r++)
            Vs[(s << 2) | r][j] = make_float2(ax[r], ay[r]);
    }
    __syncthreads();

    // ---- 3. A_q[i][j] = Re( i^(popc(i)-popc(j)) * sum_m conj(V[m,i]) z_q(m) V[m,j] ) ----
    for (int tt = t; tt < 1024; tt += 832) {
        int q = tt >> 8;
        int i = (tt >> 4) & 15;
        int j = tt & 15;
        int zmask = 8 >> q;
        float sx = 0.f, sy = 0.f;
#pragma unroll
        for (int m = 0; m < 16; m++) {
            float2 vi = Vs[m][i];
            float2 vj = Vs[m][j];
            float zz = (m & zmask) ? -1.f : 1.f;
            sx += zz * (vi.x * vj.x + vi.y * vj.y);
            sy += zz * (vi.x * vj.y - vi.y * vj.x);
        }
        int d = (__popc(i) - __popc(j)) & 3;
        Aq[q][i][j] = (d == 0) ? sx : (d == 1) ? -sy : (d == 2) ? -sx : sy;
    }
    __syncthreads();

    // ---- 4. circuit phase: thread (patch p, q) computes e_q = m^T A_q m ----
    if (t < 800) {
        int p = t >> 2;
        if (p > 195) p = 195;           // clamp dummy lanes of warp 24
        const int s = t & 3;            // doubles as the pixel index and q index
        const int pi = p / 14, pj = p - pi * 14;

        const float* xb = x + b * 784 + (2 * pi) * 28 + 2 * pj;
        float xpix = xb[(s >> 1) * 28 + (s & 1)];
        float hs_l, hc_l;
        __sincosf(CUDART_PI_F * xpix, &hs_l, &hc_l);

        const int base = (t & 31) & ~3;
        float hc0 = __shfl_sync(FULL, hc_l, base + 0), hs0 = __shfl_sync(FULL, hs_l, base + 0);
        float hc1 = __shfl_sync(FULL, hc_l, base + 1), hs1 = __shfl_sync(FULL, hs_l, base + 1);
        float hc2 = __shfl_sync(FULL, hc_l, base + 2), hs2 = __shfl_sync(FULL, hs_l, base + 2);
        float hc3 = __shfl_sync(FULL, hc_l, base + 3), hs3 = __shfl_sync(FULL, hs_l, base + 3);

        // m_i = prod_k (bit_k ? sin : cos), i bits = (q0 q1 q2 q3), q0 <-> mask 8
        float m01[4], m23[4], m[16];
        m01[0] = hc0 * hc1; m01[1] = hc0 * hs1; m01[2] = hs0 * hc1; m01[3] = hs0 * hs1;
        m23[0] = hc2 * hc3; m23[1] = hc2 * hs3; m23[2] = hs2 * hc3; m23[3] = hs2 * hs3;
#pragma unroll
        for (int i = 0; i < 16; i++)
            m[i] = m01[i >> 2] * m23[i & 3];

        // e = sum_i m_i * (A[s] row i . m)
        float e = 0.f;
#pragma unroll
        for (int i = 0; i < 16; i++) {
            const float4* Ai = reinterpret_cast<const float4*>(&Aq[s][i][0]);
            float4 a0 = Ai[0], a1 = Ai[1], a2 = Ai[2], a3 = Ai[3];
            float d0 = a0.x*m[0]  + a0.y*m[1]  + a0.z*m[2]  + a0.w*m[3];
            float d1 = a1.x*m[4]  + a1.y*m[5]  + a1.z*m[6]  + a1.w*m[7];
            float d2 = a2.x*m[8]  + a2.y*m[9]  + a2.z*m[10] + a2.w*m[11];
            float d3 = a3.x*m[12] + a3.y*m[13] + a3.z*m[14] + a3.w*m[15];
            e = fmaf(m[i], (d0 + d1) + (d2 + d3), e);
        }
        if (t < 784)
            feats[p * 4 + s] = e;
    }

    // ---- wait for weight prefetch + feat visibility ----
    asm volatile("cp.async.wait_group 0;\n" ::: "memory");
    __syncthreads();

    const int warp = t >> 5, lane = t & 31;

    // ---- 5. fc1: warps 0..15, 4 neurons each, everything from smem ----
    if (warp < 16) {
        int n0 = warp * 4;
        const float4* fv  = reinterpret_cast<const float4*>(feats);
        const float4* wv0 = reinterpret_cast<const float4*>(w1s + (n0 + 0) * NFEAT);
        const float4* wv1 = reinterpret_cast<const float4*>(w1s + (n0 + 1) * NFEAT);
        const float4* wv2 = reinterpret_cast<const float4*>(w1s + (n0 + 2) * NFEAT);
        const float4* wv3 = reinterpret_cast<const float4*>(w1s + (n0 + 3) * NFEAT);

        float a0 = 0.f, a1 = 0.f, a2 = 0.f, a3 = 0.f;
        if (lane < 28) {
#pragma unroll
            for (int j = 0; j < 7; j++) {
                int k = j * 28 + lane;
                float4 fa = fv[k];
                float4 w0 = wv0[k], w1v = wv1[k], w2v = wv2[k], w3v = wv3[k];
                a0 = fmaf(fa.x, w0.x,  fmaf(fa.y, w0.y,  fmaf(fa.z, w0.z,  fmaf(fa.w, w0.w,  a0))));
                a1 = fmaf(fa.x, w1v.x, fmaf(fa.y, w1v.y, fmaf(fa.z, w1v.z, fmaf(fa.w, w1v.w, a1))));
                a2 = fmaf(fa.x, w2v.x, fmaf(fa.y, w2v.y, fmaf(fa.z, w2v.z, fmaf(fa.w, w2v.w, a2))));
                a3 = fmaf(fa.x, w3v.x, fmaf(fa.y, w3v.y, fmaf(fa.z, w3v.z, fmaf(fa.w, w3v.w, a3))));
            }
        }
#pragma unroll
        for (int off = 16; off > 0; off >>= 1) {
            a0 += __shfl_xor_sync(FULL, a0, off);
            a1 += __shfl_xor_sync(FULL, a1, off);
            a2 += __shfl_xor_sync(FULL, a2, off);
            a3 += __shfl_xor_sync(FULL, a3, off);
        }
        if (lane == 0) {
            hids[n0 + 0] = fmaxf(a0 + b1s[n0 + 0], 0.f);
            hids[n0 + 1] = fmaxf(a1 + b1s[n0 + 1], 0.f);
            hids[n0 + 2] = fmaxf(a2 + b1s[n0 + 2], 0.f);
            hids[n0 + 3] = fmaxf(a3 + b1s[n0 + 3], 0.f);
        }
    }
    __syncthreads();

    // ---- 6. fc2: warps 0..9, one output each ----
    if (warp < 10) {
        float acc = 0.f;
        if (lane < 16) {
            float4 h  = reinterpret_cast<const float4*>(hids)[lane];
            float4 ww = reinterpret_cast<const float4*>(w2s + warp * NHID)[lane];
            acc = h.x * ww.x + h.y * ww.y + h.z * ww.z + h.w * ww.w;
        }
#pragma unroll
        for (int off = 8; off > 0; off >>= 1)
            acc += __shfl_xor_sync(FULL, acc, off);
        if (lane == 0)
            out[b * 10 + warp] = acc + b2[warp];
    }
}

extern "C" void kernel_launch(void* const* d_in, const int* in_sizes, int n_in,
                              void* d_out, int out_size) {
    const float* x     = (const float*)d_in[0];
    const float* w     = (const float*)d_in[1];
    const float* fc1_w = (const float*)d_in[2];
    const float* fc1_b = (const float*)d_in[3];
    const float* fc2_w = (const float*)d_in[4];
    const float* fc2_b = (const float*)d_in[5];
    float* out = (float*)d_out;

    cudaFuncSetAttribute(fused_kernel,
                         cudaFuncAttributeMaxDynamicSharedMemorySize, SMEM_TOTAL);
    fused_kernel<<<BATCH, 832, SMEM_TOTAL>>>(x, w, fc1_w, fc1_b, fc2_w, fc2_b, out);
}

// round 16
// speedup vs baseline: 1.8598x; 1.4508x over previous
#include <cuda_runtime.h>
#include <math_constants.h>

#define LPATCH  (14*14)
#define BATCH   128
#define NFEAT   784
#define NHID    64

// Dynamic smem layout (bytes)
#define FEAT_OFF 0               // 784 floats = 3136 B
#define W1_OFF   3136            // 64*784 floats = 200704 B
#define W2_OFF   203840          // 10*64 floats = 2560 B
#define B1_OFF   206400          // 64 floats
#define HID_OFF  206656          // 64 floats
#define SMEM_TOTAL 206912

__device__ __forceinline__ void cp_async16(void* sptr, const void* gptr) {
    unsigned s = (unsigned)__cvta_generic_to_shared(sptr);
    asm volatile("cp.async.cg.shared.global [%0], [%1], 16;\n" :: "r"(s), "l"(gptr));
}

// Full complex 2x2 on an in-register amplitude pair (proven R7 code)
#define LOCAL_GATE(u, lox, loy, hix, hiy) do {                        \
    float _lx = (u).x*(lox) + (u).y*(loy) - (u).z*(hix) - (u).w*(hiy);\
    float _ly = (u).x*(loy) - (u).y*(lox) - (u).z*(hiy) + (u).w*(hix);\
    float _hx = (u).z*(lox) - (u).w*(loy) + (u).x*(hix) - (u).y*(hiy);\
    float _hy = (u).z*(loy) + (u).w*(lox) + (u).x*(hiy) + (u).y*(hix);\
    (lox)=_lx; (loy)=_ly; (hix)=_hx; (hiy)=_hy;                       \
} while (0)

// One block per batch row: 832 threads.
// Phase 0: cp.async prefetch w1/w2/b1 (drains during phases 1-3)
// Phase 1: um[20] gate constants
// Phase 2: warps 0-1 simulate the 16 columns of V (all 5 layers); write
//          Vw[i][j] = V[i][j] * (-i)^popc(j) into a bank-padded smem layout
// Phase 3: circuit = factored matvec y = Vw (v0 x v1 x v2 x v3);
//          e_q = sum_i z_q(i) |y_i|^2.  4 threads/patch, 4 rows each.
// Phase 4: fc1 from smem; Phase 5: fc2
__global__ void __launch_bounds__(832, 1) fused_kernel(
    const float* __restrict__ x,      // [128,1,28,28]
    const float* __restrict__ w,      // [60]
    const float* __restrict__ w1,     // [64,784]
    const float* __restrict__ b1,     // [64]
    const float* __restrict__ w2,     // [10,64]
    const float* __restrict__ b2,     // [10]
    float* __restrict__ out)          // [128,10]
{
    extern __shared__ char smem_raw[];
    float* feats = reinterpret_cast<float*>(smem_raw + FEAT_OFF);
    float* w1s   = reinterpret_cast<float*>(smem_raw + W1_OFF);
    float* w2s   = reinterpret_cast<float*>(smem_raw + W2_OFF);
    float* b1s   = reinterpret_cast<float*>(smem_raw + B1_OFF);
    float* hids  = reinterpret_cast<float*>(smem_raw + HID_OFF);

    __shared__ float4 um[20];                        // fused yzy, 5 layers x 4 qubits
    // Vw rows padded to 72 floats (288 B): 16B-aligned rows; 4-row stride
    // = 72*4 = 288 floats = 8 mod 32 banks -> the 4 s-groups are conflict-free.
    __shared__ __align__(16) float Vwp[16][72];

    const int t = threadIdx.x;
    const int b = blockIdx.x;
    const unsigned FULL = 0xffffffffu;

    // ---- 0. fire-and-forget weight prefetch ----
    for (int i = t; i < (NHID * NFEAT) / 4; i += 832)
        cp_async16(w1s + i * 4, w1 + i * 4);
    if (t < 160) cp_async16(w2s + t * 4, w2 + t * 4);
    if (t < 16)  cp_async16(b1s + t * 4, b1 + t * 4);
    asm volatile("cp.async.commit_group;\n" ::: "memory");

    // ---- 1. gate constants: fused U = Ry(c)Rz(b)Ry(a) per (layer, qubit) ----
    if (t < 20) {
        int l = t >> 2, q = t & 3;
        float a = w[l * 12 + q], bb = w[l * 12 + 4 + q], c = w[l * 12 + 8 + q];
        float sP, cP, sQ, cQ, sB, cB;
        sincosf(0.5f * (a + c), &sP, &cP);
        sincosf(0.5f * (a - c), &sQ, &cQ);
        sincosf(0.5f * bb,      &sB, &cB);
        um[t] = make_float4(cB * cP, sB * cQ, cB * sP, sB * sQ);
    }
    __syncthreads();

    // ---- 2. simulate V columns: thread (col j = t>>2, s = t&3), amps i=(s<<2)|r ----
    if (t < 64) {
        const int j = t >> 2;
        const int s = t & 3;
        float ax[4], ay[4];
#pragma unroll
        for (int r = 0; r < 4; r++) {
            ax[r] = (((s << 2) | r) == j) ? 1.f : 0.f;
            ay[r] = 0.f;
        }
#pragma unroll
        for (int l = 0; l < 5; l++) {
            {   // gate q0 (amp bit 3 = thread bit 1 of s... s&2, shfl mask 2)
                float4 u = um[l * 4 + 0];
                bool bt = (s & 2) != 0;
                float sy = bt ? u.y : -u.y;
                float sz = bt ? u.z : -u.z;
#pragma unroll
                for (int r = 0; r < 4; r++) {
                    float px = __shfl_xor_sync(FULL, ax[r], 2);
                    float py = __shfl_xor_sync(FULL, ay[r], 2);
                    float nx_ = u.x * ax[r] - sy * ay[r] + sz * px - u.w * py;
                    float ny_ = u.x * ay[r] + sy * ax[r] + sz * py + u.w * px;
                    ax[r] = nx_; ay[r] = ny_;
                }
            }
            {   // gate q1 (s&1, shfl mask 1)
                float4 u = um[l * 4 + 1];
                bool bt = (s & 1) != 0;
                float sy = bt ? u.y : -u.y;
                float sz = bt ? u.z : -u.z;
#pragma unroll
                for (int r = 0; r < 4; r++) {
                    float px = __shfl_xor_sync(FULL, ax[r], 1);
                    float py = __shfl_xor_sync(FULL, ay[r], 1);
                    float nx_ = u.x * ax[r] - sy * ay[r] + sz * px - u.w * py;
                    float ny_ = u.x * ay[r] + sy * ax[r] + sz * py + u.w * px;
                    ax[r] = nx_; ay[r] = ny_;
                }
            }
            {   // local gates q2, q3
                float4 u2 = um[l * 4 + 2];
                LOCAL_GATE(u2, ax[0], ay[0], ax[2], ay[2]);
                LOCAL_GATE(u2, ax[1], ay[1], ax[3], ay[3]);
                float4 u3 = um[l * 4 + 3];
                LOCAL_GATE(u3, ax[0], ay[0], ax[1], ay[1]);
                LOCAL_GATE(u3, ax[2], ay[2], ax[3], ay[3]);
            }
            if (l < 4) {    // CNOT ring
#pragma unroll
                for (int r = 0; r < 4; r++) {      // C(q0->q1)
                    float px = __shfl_xor_sync(FULL, ax[r], 1);
                    float py = __shfl_xor_sync(FULL, ay[r], 1);
                    if (s & 2) { ax[r] = px; ay[r] = py; }
                }
                if (s & 1) {                        // C(q1->q2)
                    float tx;
                    tx = ax[0]; ax[0] = ax[2]; ax[2] = tx;
                    tx = ay[0]; ay[0] = ay[2]; ay[2] = tx;
                    tx = ax[1]; ax[1] = ax[3]; ax[3] = tx;
                    tx = ay[1]; ay[1] = ay[3]; ay[3] = tx;
                }
                {                                   // C(q2->q3)
                    float tx;
                    tx = ax[2]; ax[2] = ax[3]; ax[3] = tx;
                    tx = ay[2]; ay[2] = ay[3]; ay[3] = tx;
                }
                // C(q3->q0)
                ax[1] = __shfl_xor_sync(FULL, ax[1], 2);
                ay[1] = __shfl_xor_sync(FULL, ay[1], 2);
                ax[3] = __shfl_xor_sync(FULL, ax[3], 2);
                ay[3] = __shfl_xor_sync(FULL, ay[3], 2);
            }
        }
        // write Vw[i][j] = V[i][j] * (-i)^popc(j)  (column phase applied here)
        int ph = __popc(j) & 3;
#pragma unroll
        for (int r = 0; r < 4; r++) {
            int i = (s << 2) | r;
            float vx = ax[r], vy = ay[r], ox, oy;
            switch (ph) {
                case 0: ox =  vx; oy =  vy; break;
                case 1: ox =  vy; oy = -vx; break;   // *(-i)
                case 2: ox = -vx; oy = -vy; break;
                default:ox = -vy; oy =  vx; break;   // *(+i)
            }
            Vwp[i][2 * j]     = ox;
            Vwp[i][2 * j + 1] = oy;
        }
    }
    __syncthreads();

    // ---- 3. circuit: y = Vw (v0 x v1 x v2 x v3);  e_q = sum z_q(i)|y_i|^2 ----
    if (t < 800) {
        int p = t >> 2;
        if (p > 195) p = 195;           // clamp dummy lanes of warp 24
        const int s = t & 3;
        const int pi = p / 14, pj = p - pi * 14;

        const float* xb = x + b * 784 + (2 * pi) * 28 + 2 * pj;
        float xpix = xb[(s >> 1) * 28 + (s & 1)];
        float sl, cl;
        __sincosf(CUDART_PI_F * xpix, &sl, &cl);

        const int base = (t & 31) & ~3;
        float c0 = __shfl_sync(FULL, cl, base + 0), s0 = __shfl_sync(FULL, sl, base + 0);
        float c1 = __shfl_sync(FULL, cl, base + 1), s1 = __shfl_sync(FULL, sl, base + 1);
        float c2 = __shfl_sync(FULL, cl, base + 2), s2 = __shfl_sync(FULL, sl, base + 2);
        float c3 = __shfl_sync(FULL, cl, base + 3), s3 = __shfl_sync(FULL, sl, base + 3);

        float pr[4];
#pragma unroll
        for (int r = 0; r < 4; r++) {
            const float4* Vr = reinterpret_cast<const float4*>(&Vwp[(s << 2) | r][0]);
            // contract q3 (bit0): float4 k = complex j=2k (x,y) and j=2k+1 (z,w)
            float t1x[8], t1y[8];
#pragma unroll
            for (int k = 0; k < 8; k++) {
                float4 A = Vr[k];
                t1x[k] = A.x * c3 + A.z * s3;
                t1y[k] = A.y * c3 + A.w * s3;
            }
            // contract q2
            float t2x[4], t2y[4];
#pragma unroll
            for (int g2 = 0; g2 < 4; g2++) {
                t2x[g2] = t1x[2 * g2] * c2 + t1x[2 * g2 + 1] * s2;
                t2y[g2] = t1y[2 * g2] * c2 + t1y[2 * g2 + 1] * s2;
            }
            // contract q1
            float t3x0 = t2x[0] * c1 + t2x[1] * s1;
            float t3y0 = t2y[0] * c1 + t2y[1] * s1;
            float t3x1 = t2x[2] * c1 + t2x[3] * s1;
            float t3y1 = t2y[2] * c1 + t2y[3] * s1;
            // contract q0
            float yx = t3x0 * c0 + t3x1 * s0;
            float yy = t3y0 * c0 + t3y1 * s0;
            pr[r] = yx * yx + yy * yy;
        }

        // z_q signs: i = (s<<2)|r; q0<->i&8=s&2, q1<->s&1, q2<->r&2, q3<->r&1
        float sum = (pr[0] + pr[1]) + (pr[2] + pr[3]);
        float e0 = (s & 2) ? -sum : sum;
        float e1 = (s & 1) ? -sum : sum;
        float e2 = (pr[0] + pr[1]) - (pr[2] + pr[3]);
        float e3 = (pr[0] - pr[1]) + (pr[2] - pr[3]);

        e0 += __shfl_xor_sync(FULL, e0, 1);
        e1 += __shfl_xor_sync(FULL, e1, 1);
        e2 += __shfl_xor_sync(FULL, e2, 1);
        e3 += __shfl_xor_sync(FULL, e3, 1);
        e0 += __shfl_xor_sync(FULL, e0, 2);
        e1 += __shfl_xor_sync(FULL, e1, 2);
        e2 += __shfl_xor_sync(FULL, e2, 2);
        e3 += __shfl_xor_sync(FULL, e3, 2);

        if (t < 784)
            feats[p * 4 + s] = (s == 0) ? e0 : (s == 1) ? e1 : (s == 2) ? e2 : e3;
    }

    // ---- wait for weight prefetch + feat visibility ----
    asm volatile("cp.async.wait_group 0;\n" ::: "memory");
    __syncthreads();

    const int warp = t >> 5, lane = t & 31;

    // ---- 4. fc1: warps 0..15, 4 neurons each, everything from smem ----
    if (warp < 16) {
        int n0 = warp * 4;
        const float4* fv  = reinterpret_cast<const float4*>(feats);
        const float4* wv0 = reinterpret_cast<const float4*>(w1s + (n0 + 0) * NFEAT);
        const float4* wv1 = reinterpret_cast<const float4*>(w1s + (n0 + 1) * NFEAT);
        const float4* wv2 = reinterpret_cast<const float4*>(w1s + (n0 + 2) * NFEAT);
        const float4* wv3 = reinterpret_cast<const float4*>(w1s + (n0 + 3) * NFEAT);

        float a0 = 0.f, a1 = 0.f, a2 = 0.f, a3 = 0.f;
        if (lane < 28) {
#pragma unroll
            for (int j = 0; j < 7; j++) {
                int k = j * 28 + lane;
                float4 fa = fv[k];
                float4 w0 = wv0[k], w1v = wv1[k], w2v = wv2[k], w3v = wv3[k];
                a0 = fmaf(fa.x, w0.x,  fmaf(fa.y, w0.y,  fmaf(fa.z, w0.z,  fmaf(fa.w, w0.w,  a0))));
                a1 = fmaf(fa.x, w1v.x, fmaf(fa.y, w1v.y, fmaf(fa.z, w1v.z, fmaf(fa.w, w1v.w, a1))));
                a2 = fmaf(fa.x, w2v.x, fmaf(fa.y, w2v.y, fmaf(fa.z, w2v.z, fmaf(fa.w, w2v.w, a2))));
                a3 = fmaf(fa.x, w3v.x, fmaf(fa.y, w3v.y, fmaf(fa.z, w3v.z, fmaf(fa.w, w3v.w, a3))));
            }
        }
#pragma unroll
        for (int off = 16; off > 0; off >>= 1) {
            a0 += __shfl_xor_sync(FULL, a0, off);
            a1 += __shfl_xor_sync(FULL, a1, off);
            a2 += __shfl_xor_sync(FULL, a2, off);
            a3 += __shfl_xor_sync(FULL, a3, off);
        }
        if (lane == 0) {
            hids[n0 + 0] = fmaxf(a0 + b1s[n0 + 0], 0.f);
            hids[n0 + 1] = fmaxf(a1 + b1s[n0 + 1], 0.f);
            hids[n0 + 2] = fmaxf(a2 + b1s[n0 + 2], 0.f);
            hids[n0 + 3] = fmaxf(a3 + b1s[n0 + 3], 0.f);
        }
    }
    __syncthreads();

    // ---- 5. fc2: warps 0..9, one output each ----
    if (warp < 10) {
        float acc = 0.f;
        if (lane < 16) {
            float4 h  = reinterpret_cast<const float4*>(hids)[lane];
            float4 ww = reinterpret_cast<const float4*>(w2s + warp * NHID)[lane];
            acc = h.x * ww.x + h.y * ww.y + h.z * ww.z + h.w * ww.w;
        }
#pragma unroll
        for (int off = 8; off > 0; off >>= 1)
            acc += __shfl_xor_sync(FULL, acc, off);
        if (lane == 0)
            out[b * 10 + warp] = acc + b2[warp];
    }
}

extern "C" void kernel_launch(void* const* d_in, const int* in_sizes, int n_in,
                              void* d_out, int out_size) {
    const float* x     = (const float*)d_in[0];
    const float* w     = (const float*)d_in[1];
    const float* fc1_w = (const float*)d_in[2];
    const float* fc1_b = (const float*)d_in[3];
    const float* fc2_w = (const float*)d_in[4];
    const float* fc2_b = (const float*)d_in[5];
    float* out = (float*)d_out;

    cudaFuncSetAttribute(fused_kernel,
                         cudaFuncAttributeMaxDynamicSharedMemorySize, SMEM_TOTAL);
    fused_kernel<<<BATCH, 832, SMEM_TOTAL>>>(x, w, fc1_w, fc1_b, fc2_w, fc2_b, out);
}